// round 2
// baseline (speedup 1.0000x reference)
#include <cuda_runtime.h>
#include <cstdint>

#define NPTS 8192
#define DIM 128
#define KM1 7
#define NROWS 57344          // 7*8192
#define NBLK4 7168           // 57344/8
#define NEG_INF (__int_as_float(0xff800000))
#define TINYF 1.17549435e-38f

// ---------------- scratch (static device globals; no allocations) ----------
__device__ float              g_mat[(size_t)NPTS * NPTS];   // W (weight) or 0
__device__ unsigned long long g_cjw[(size_t)NPTS * NPTS];   // packed (W,j) compact lists
__device__ int                g_cnt[NPTS];
__device__ float              g_sq[NPTS];
__device__ int                g_samp[NROWS];
__device__ double             g_ploss[NBLK4];
__device__ float              g_pcnt[NBLK4];

// ---- threefry2x32, key=(0,42), counter=(0, c1)  [partitionable mode] -------
// returns out0 ^ out1 (JAX partitionable 32-bit random_bits)
__device__ __forceinline__ uint32_t tf_bits(uint32_t c1) {
    const uint32_t k0 = 0u;
    const uint32_t k1 = 42u;
    const uint32_t k2 = 0x1BD11BDAu ^ 42u;
    uint32_t x0 = 0u;               // c0 = 0, +k0 = 0
    uint32_t x1 = c1 + k1;
#define TFR(r) x0 += x1; x1 = __funnelshift_l(x1, x1, r); x1 ^= x0;
    TFR(13) TFR(15) TFR(26) TFR(6)   x0 += k1; x1 += k2 + 1u;
    TFR(17) TFR(29) TFR(16) TFR(24)  x0 += k2; x1 += k0 + 2u;
    TFR(13) TFR(15) TFR(26) TFR(6)   x0 += k0; x1 += k1 + 3u;
    TFR(17) TFR(29) TFR(16) TFR(24)  x0 += k1; x1 += k2 + 4u;
    TFR(13) TFR(15) TFR(26) TFR(6)   x0 += k2; x1 += k0 + 5u;
#undef TFR
    return x0 ^ x1;
}

// t = -log(max(f, tiny)), f in [0,1). Precise for f->1 via atanh series.
__device__ __forceinline__ float neg_log_u(float f) {
    // series path (f > 0.75): log1p(r) = 2*atanh(s), s = r/(2+r), r = f-1 exact
    float r  = f - 1.0f;
    float s  = __fdividef(r, 2.0f + r);
    float s2 = s * s;
    float tp = -2.0f * s * (1.0f + s2 * (0.33333334f + s2 * (0.2f + s2 * 0.14285715f)));
    // fast path
    float u  = fmaxf(f, TINYF);
    float tf = -__logf(u);
    return (f > 0.75f) ? tp : tf;
}

// ---------------- K0: row squared norms -------------------------------------
__global__ void k0_sq(const float* __restrict__ x) {
    __shared__ float red[128];
    int i = blockIdx.x;
    float v = x[(size_t)i * DIM + threadIdx.x];
    red[threadIdx.x] = v * v;
    __syncthreads();
    for (int s = 64; s > 0; s >>= 1) {
        if (threadIdx.x < s) red[threadIdx.x] += red[threadIdx.x + s];
        __syncthreads();
    }
    if (threadIdx.x == 0) g_sq[i] = red[0];
}

// ---------------- K1: 128x128-tile gram -> masked weight W ------------------
__global__ __launch_bounds__(256) void k1_dist(const float* __restrict__ x) {
    __shared__ float As[32][132];
    __shared__ float Bs[32][132];
    int row0 = blockIdx.y * 128, col0 = blockIdx.x * 128;
    int t = threadIdx.x;
    float acc[8][8];
#pragma unroll
    for (int a = 0; a < 8; a++)
#pragma unroll
        for (int b = 0; b < 8; b++) acc[a][b] = 0.f;
    int tm0 = (t >> 4) * 8, tn0 = (t & 15) * 8;

    for (int kc = 0; kc < DIM; kc += 32) {
#pragma unroll
        for (int it = 0; it < 4; it++) {
            int f  = it * 256 + t;
            int r  = f >> 3;
            int c4 = (f & 7) << 2;
            float4 va = *(const float4*)(x + (size_t)(row0 + r) * DIM + kc + c4);
            As[c4][r] = va.x; As[c4 + 1][r] = va.y; As[c4 + 2][r] = va.z; As[c4 + 3][r] = va.w;
            float4 vb = *(const float4*)(x + (size_t)(col0 + r) * DIM + kc + c4);
            Bs[c4][r] = vb.x; Bs[c4 + 1][r] = vb.y; Bs[c4 + 2][r] = vb.z; Bs[c4 + 3][r] = vb.w;
        }
        __syncthreads();
#pragma unroll
        for (int k = 0; k < 32; k++) {
            float a[8], b[8];
            *(float4*)(a)     = *(const float4*)&As[k][tm0];
            *(float4*)(a + 4) = *(const float4*)&As[k][tm0 + 4];
            *(float4*)(b)     = *(const float4*)&Bs[k][tn0];
            *(float4*)(b + 4) = *(const float4*)&Bs[k][tn0 + 4];
#pragma unroll
            for (int m = 0; m < 8; m++)
#pragma unroll
                for (int n = 0; n < 8; n++)
                    acc[m][n] = fmaf(a[m], b[n], acc[m][n]);
        }
        __syncthreads();
    }

#pragma unroll
    for (int m = 0; m < 8; m++) {
        int i = row0 + tm0 + m;
        float sqi = g_sq[i];
        int ib = i >> 3;
        float out[8];
#pragma unroll
        for (int n = 0; n < 8; n++) {
            int j = col0 + tn0 + n;
            float q = sqi + g_sq[j] - 2.f * acc[m][n];
            float d = fmaxf(sqrtf(q), 0.5f);       // NaN on diag -> 0.5, masked anyway
            bool valid = ((j >> 3) != ib) && (d < 1.4f);
            float W = 0.f;
            if (valid)
                W = __expf(-126.f * __logf(d) - 62.5f * __logf(1.f - 0.25f * d * d));
            out[n] = W;
        }
        float4* dst = (float4*)(g_mat + (size_t)i * NPTS + col0 + tn0);
        dst[0] = *(float4*)out;
        dst[1] = *(float4*)(out + 4);
    }
}

// ---------------- K2: per-row ordered stream compaction ---------------------
__global__ __launch_bounds__(256) void k2_compact() {
    int i = blockIdx.x;
    const float* __restrict__ row = g_mat + (size_t)i * NPTS;
    unsigned long long* __restrict__ dst = g_cjw + (size_t)i * NPTS;
    __shared__ int warp_off[8];
    __shared__ int base_off;
    if (threadIdx.x == 0) base_off = 0;
    int lane = threadIdx.x & 31, wid = threadIdx.x >> 5;
    __syncthreads();
    for (int c = 0; c < NPTS; c += 256) {
        int j = c + threadIdx.x;
        float W = row[j];
        bool v = W > 0.f;
        unsigned bal = __ballot_sync(0xffffffffu, v);
        int pre = __popc(bal & ((1u << lane) - 1u));
        int tot = __popc(bal);
        __syncthreads();                 // previous iteration readers done
        if (lane == 0) warp_off[wid] = tot;
        __syncthreads();
        if (threadIdx.x == 0) {
            int s = base_off;
            for (int w = 0; w < 8; w++) { int tw = warp_off[w]; warp_off[w] = s; s += tw; }
            base_off = s;
        }
        __syncthreads();
        if (v)
            dst[warp_off[wid] + pre] =
                ((unsigned long long)__float_as_uint(W) << 32) | (unsigned)j;
    }
    __syncthreads();
    if (threadIdx.x == 0) g_cnt[i] = base_off;
}

// ---------------- K3: 7-sample gumbel argmax per anchor ---------------------
// counter index = (s*8192 + i)*8192 + j = s*2^26 + i*2^13 + j   (< 2^32)
__global__ __launch_bounds__(256) void k3_sample() {
    int i = blockIdx.x;
    int cnt = g_cnt[i];
    const unsigned long long* __restrict__ lst = g_cjw + (size_t)i * NPTS;
    unsigned base_i = (unsigned)i << 13;

    float bv[KM1];
    int   bj[KM1];
#pragma unroll
    for (int s = 0; s < KM1; s++) { bv[s] = -1.0f; bj[s] = 0x7FFFFFFF; }

    if (cnt > 0) {
        for (int p = threadIdx.x; p < cnt; p += 256) {
            unsigned long long e = lst[p];
            unsigned j = (unsigned)e;
            float W = __uint_as_float((unsigned)(e >> 32));
            unsigned cbase = base_i + j;
#pragma unroll
            for (int s = 0; s < KM1; s++) {
                uint32_t b = tf_bits(cbase + (unsigned)s * 67108864u);
                float f = __uint_as_float((b >> 9) | 0x3f800000u) - 1.0f;
                float t = neg_log_u(f);
                float v = __fdividef(W, t);
                if (v > bv[s]) { bv[s] = v; bj[s] = (int)j; }
            }
        }
    } else {
        // row_ok fallback: logits all 0 -> argmax of pure gumbel
        for (int p = threadIdx.x; p < NPTS; p += 256) {
            unsigned cbase = base_i + (unsigned)p;
#pragma unroll
            for (int s = 0; s < KM1; s++) {
                uint32_t b = tf_bits(cbase + (unsigned)s * 67108864u);
                float f = __uint_as_float((b >> 9) | 0x3f800000u) - 1.0f;
                float t = neg_log_u(f);
                float v = __fdividef(1.0f, t);
                if (v > bv[s]) { bv[s] = v; bj[s] = p; }
            }
        }
    }

    __shared__ float sv[256];
    __shared__ int   si[256];
#pragma unroll
    for (int s = 0; s < KM1; s++) {
        __syncthreads();
        sv[threadIdx.x] = bv[s]; si[threadIdx.x] = bj[s];
        __syncthreads();
        for (int off = 128; off > 0; off >>= 1) {
            if (threadIdx.x < off) {
                float v = sv[threadIdx.x + off];
                int  jj = si[threadIdx.x + off];
                if (v > sv[threadIdx.x] || (v == sv[threadIdx.x] && jj < si[threadIdx.x])) {
                    sv[threadIdx.x] = v; si[threadIdx.x] = jj;
                }
            }
            __syncthreads();
        }
        if (threadIdx.x == 0) g_samp[s * NPTS + i] = si[0];
    }
}

// ---------------- K4: triplet losses, one warp per pair ---------------------
__global__ __launch_bounds__(256) void k4_pairs(const float* __restrict__ x,
                                                const float* __restrict__ beta) {
    int wid  = threadIdx.x >> 5;
    int lane = threadIdx.x & 31;
    int pair = blockIdx.x * 8 + wid;          // < 57344
    int i = pair / 7;
    int s = pair - i * 7;
    int ii = i & 7;
    int p  = (i & ~7) + (s < ii ? s : s + 1); // positives in block order, self excluded
    int nn = g_samp[s * NPTS + i];            // samples.T.reshape(-1)

    const float4* xa = (const float4*)(x + (size_t)i  * DIM);
    const float4* xp = (const float4*)(x + (size_t)p  * DIM);
    const float4* xn = (const float4*)(x + (size_t)nn * DIM);
    float4 a = xa[lane], pv = xp[lane], nv = xn[lane];
    float dap = (a.x - pv.x) * (a.x - pv.x) + (a.y - pv.y) * (a.y - pv.y)
              + (a.z - pv.z) * (a.z - pv.z) + (a.w - pv.w) * (a.w - pv.w);
    float dan = (a.x - nv.x) * (a.x - nv.x) + (a.y - nv.y) * (a.y - nv.y)
              + (a.z - nv.z) * (a.z - nv.z) + (a.w - nv.w) * (a.w - nv.w);
    for (int off = 16; off; off >>= 1) {
        dap += __shfl_down_sync(0xffffffffu, dap, off);
        dan += __shfl_down_sync(0xffffffffu, dan, off);
    }

    __shared__ double sl[8];
    __shared__ float  sc[8];
    if (lane == 0) {
        float b    = beta[i];
        float d_ap = sqrtf(dap + 1e-8f);
        float d_an = sqrtf(dan + 1e-8f);
        float pos  = fmaxf(d_ap - b + 0.2f, 0.f);
        float neg  = fmaxf(b - d_an + 0.2f, 0.f);
        sl[wid] = (double)(pos + neg);
        sc[wid] = (pos > 0.f ? 1.f : 0.f) + (neg > 0.f ? 1.f : 0.f);
    }
    __syncthreads();
    if (threadIdx.x == 0) {
        double L = 0; float C = 0;
        for (int w = 0; w < 8; w++) { L += sl[w]; C += sc[w]; }
        g_ploss[blockIdx.x] = L;
        g_pcnt[blockIdx.x]  = C;
    }
}

// ---------------- K5: deterministic final reduction --------------------------
__global__ void k5_final(float* out) {
    __shared__ double sd[256];
    __shared__ float  scn[256];
    double L = 0; float C = 0;
    for (int idx = threadIdx.x; idx < NBLK4; idx += 256) {
        L += g_ploss[idx];
        C += g_pcnt[idx];
    }
    sd[threadIdx.x] = L; scn[threadIdx.x] = C;
    __syncthreads();
    for (int s = 128; s > 0; s >>= 1) {
        if (threadIdx.x < s) {
            sd[threadIdx.x]  += sd[threadIdx.x + s];
            scn[threadIdx.x] += scn[threadIdx.x + s];
        }
        __syncthreads();
    }
    if (threadIdx.x == 0) out[0] = (float)(sd[0] / (double)scn[0]);
}

// ---------------- launch -----------------------------------------------------
extern "C" void kernel_launch(void* const* d_in, const int* in_sizes, int n_in,
                              void* d_out, int out_size) {
    const float* x    = (const float*)d_in[0];   // [8192,128] f32
    const float* beta = (const float*)d_in[2];   // [8192] f32 (d_in[1] = y, unused)

    k0_sq<<<NPTS, 128>>>(x);
    dim3 g1(64, 64);
    k1_dist<<<g1, 256>>>(x);
    k2_compact<<<NPTS, 256>>>();
    k3_sample<<<NPTS, 256>>>();
    k4_pairs<<<NBLK4, 256>>>(x, beta);
    k5_final<<<1, 256>>>((float*)d_out);
}